// round 3
// baseline (speedup 1.0000x reference)
#include <cuda_runtime.h>
#include <cuda_bf16.h>
#include <cstdint>
#include <cstddef>

// ---------------------------------------------------------------------------
// Problem sizes
// ---------------------------------------------------------------------------
constexpr int NI = 16;      // instances
constexpr int SQ = 2048;    // sequence
constexpr int HH = 1024;    // hidden
constexpr int KE = 8;       // experts
constexpr int DB = 256;     // bottleneck

// ---------------------------------------------------------------------------
// Device scratch (static globals -- no allocations allowed)
// ---------------------------------------------------------------------------
__device__ __nv_bfloat16 g_wd[(size_t)NI * DB * HH];   // merged down weights [n][d][h]
__device__ __nv_bfloat16 g_wu[(size_t)NI * HH * DB];   // merged up   weights [n][h][d]
__device__ float         g_bd[NI * DB];
__device__ float         g_bu[NI * HH];
__device__ __nv_bfloat16 g_y1[(size_t)NI * SQ * DB];   // relu(down(x)) bf16 [n][s][d]

// ---------------------------------------------------------------------------
// Helpers
// ---------------------------------------------------------------------------
#define DEVINL __device__ __forceinline__

DEVINL uint32_t smem_u32(const void* p) {
    uint32_t a;
    asm("{ .reg .u64 t; cvta.to.shared.u64 t, %1; cvt.u32.u64 %0, t; }" : "=r"(a) : "l"(p));
    return a;
}
DEVINL uint32_t packbf2(float lo, float hi) {
    uint32_t r;
    asm("cvt.rn.bf16x2.f32 %0, %1, %2;" : "=r"(r) : "f"(hi), "f"(lo));
    return r;
}

#define SW128(o) ((o) ^ (((o) >> 3) & 0x70))

DEVINL void ldsm4(uint32_t& r0, uint32_t& r1, uint32_t& r2, uint32_t& r3, uint32_t addr) {
    asm volatile("ldmatrix.sync.aligned.m8n8.x4.shared.b16 {%0,%1,%2,%3}, [%4];"
                 : "=r"(r0), "=r"(r1), "=r"(r2), "=r"(r3) : "r"(addr));
}
DEVINL void mma16816(float* d, const uint32_t* a, uint32_t b0, uint32_t b1) {
    asm volatile(
        "mma.sync.aligned.m16n8k16.row.col.f32.bf16.bf16.f32 "
        "{%0,%1,%2,%3}, {%4,%5,%6,%7}, {%8,%9}, {%0,%1,%2,%3};"
        : "+f"(d[0]), "+f"(d[1]), "+f"(d[2]), "+f"(d[3])
        : "r"(a[0]), "r"(a[1]), "r"(a[2]), "r"(a[3]), "r"(b0), "r"(b1));
}
DEVINL void cp16(uint32_t dst, const void* src) {
    asm volatile("cp.async.cg.shared.global [%0], [%1], 16;" :: "r"(dst), "l"(src));
}
#define CP_COMMIT() asm volatile("cp.async.commit_group;" ::: "memory")
template <int N> DEVINL void cp_wait() {
    asm volatile("cp.async.wait_group %0;" :: "n"(N) : "memory");
}

// ---------------------------------------------------------------------------
// SMEM layout (dynamic): A stages [0,32K), B stages [32K,64K), bias at 66K.
// Epilogue reuses [0, ~35K).
// ---------------------------------------------------------------------------
constexpr uint32_t STG_SZ   = 128 * 128;         // 16 KB per operand stage
constexpr uint32_t OFF_B0   = 2 * STG_SZ;        // 32 KB
constexpr uint32_t OFF_BIAS = 66 * 1024;
constexpr uint32_t SMEM_TOTAL = 68 * 1024;

// ---------------------------------------------------------------------------
// Weight / bias merge kernels
// ---------------------------------------------------------------------------
constexpr int E2 = DB * HH / 2;   // float2 elements per expert

__global__ void merge_wd_kernel(const float* __restrict__ w, const float* __restrict__ prob) {
    __shared__ float p[NI * KE];
    if (threadIdx.x < NI * KE) p[threadIdx.x] = prob[threadIdx.x];
    __syncthreads();
    int e2 = blockIdx.x * 256 + threadIdx.x;
    const float2* w2 = reinterpret_cast<const float2*>(w);
    float2 wv[KE];
#pragma unroll
    for (int k = 0; k < KE; ++k) wv[k] = w2[(size_t)k * E2 + e2];
    uint32_t* out = reinterpret_cast<uint32_t*>(g_wd);
#pragma unroll
    for (int n = 0; n < NI; ++n) {
        float x = 0.f, y = 0.f;
#pragma unroll
        for (int k = 0; k < KE; ++k) {
            x = fmaf(p[n * KE + k], wv[k].x, x);
            y = fmaf(p[n * KE + k], wv[k].y, y);
        }
        out[(size_t)n * E2 + e2] = packbf2(x, y);
    }
}

__global__ void merge_wu_kernel(const float* __restrict__ w, const float* __restrict__ prob) {
    __shared__ float p[NI * KE];
    if (threadIdx.x < NI * KE) p[threadIdx.x] = prob[threadIdx.x];
    __syncthreads();
    int e2 = blockIdx.x * 256 + threadIdx.x;
    const float2* w2 = reinterpret_cast<const float2*>(w);
    float2 wv[KE];
#pragma unroll
    for (int k = 0; k < KE; ++k) wv[k] = w2[(size_t)k * E2 + e2];
    uint32_t* out = reinterpret_cast<uint32_t*>(g_wu);
#pragma unroll
    for (int n = 0; n < NI; ++n) {
        float x = 0.f, y = 0.f;
#pragma unroll
        for (int k = 0; k < KE; ++k) {
            x = fmaf(p[n * KE + k], wv[k].x, x);
            y = fmaf(p[n * KE + k], wv[k].y, y);
        }
        out[(size_t)n * E2 + e2] = packbf2(x, y);
    }
}

__global__ void merge_b_kernel(const float* __restrict__ bd_in,
                               const float* __restrict__ bu_in,
                               const float* __restrict__ prob) {
    int g = blockIdx.x * 256 + threadIdx.x;
    if (g >= NI * (DB + HH)) return;
    int n = g / (DB + HH);
    int j = g % (DB + HH);
    float acc = 0.f;
    if (j < DB) {
#pragma unroll
        for (int k = 0; k < KE; ++k) acc = fmaf(prob[n * KE + k], bd_in[k * DB + j], acc);
        g_bd[n * DB + j] = acc;
    } else {
        int jj = j - DB;
#pragma unroll
        for (int k = 0; k < KE; ++k) acc = fmaf(prob[n * KE + k], bu_in[k * HH + jj], acc);
        g_bu[n * HH + jj] = acc;
    }
}

// ---------------------------------------------------------------------------
// Shared compute: warp tile 32(m) x 64(n), CTA tile 128x128, BK=64, 8 warps.
// acc[mi 0..1][ni 0..7][4]
// ---------------------------------------------------------------------------
struct WarpId { int lane, wm, wn; };

DEVINL void compute_stage(uint32_t sbase, int s, const WarpId& w, float acc[2][8][4]) {
    uint32_t abase = sbase + (uint32_t)s * STG_SZ;
    uint32_t bbase = sbase + OFF_B0 + (uint32_t)s * STG_SZ;
#pragma unroll
    for (int ks = 0; ks < 4; ++ks) {
        uint32_t a[2][4];
        {
            int r = w.wm * 32 + (w.lane & 15);
            uint32_t co = (uint32_t)(ks * 32 + ((w.lane >> 4) << 4));
            uint32_t o0 = (uint32_t)(r * 128) + co;
            uint32_t o1 = (uint32_t)((r + 16) * 128) + co;
            ldsm4(a[0][0], a[0][1], a[0][2], a[0][3], abase + SW128(o0));
            ldsm4(a[1][0], a[1][1], a[1][2], a[1][3], abase + SW128(o1));
        }
#pragma unroll
        for (int g = 0; g < 4; ++g) {
            int br = w.wn * 64 + g * 16 + (w.lane & 7) + ((w.lane >> 4) & 1) * 8;
            uint32_t bco = (uint32_t)(ks * 32 + ((w.lane >> 3) & 1) * 16);
            uint32_t q0, q1, q2, q3;
            ldsm4(q0, q1, q2, q3, bbase + SW128((uint32_t)(br * 128) + bco));
            mma16816(acc[0][2 * g],     a[0], q0, q1);
            mma16816(acc[0][2 * g + 1], a[0], q2, q3);
            mma16816(acc[1][2 * g],     a[1], q0, q1);
            mma16816(acc[1][2 * g + 1], a[1], q2, q3);
        }
    }
}

// cp.async one 128x64-bf16 tile (row stride `ld` elements) into stage s of region off0
DEVINL void cp_tile(uint32_t sbase, uint32_t off0, int s, const __nv_bfloat16* src,
                    int ld, int kofs, int tid) {
    uint32_t dst0 = sbase + off0 + (uint32_t)s * STG_SZ;
#pragma unroll
    for (int i = 0; i < 4; ++i) {
        int idx = tid + i * 256;
        int row = idx >> 3, seg = idx & 7;
        uint32_t o = (uint32_t)(row * 128 + seg * 16);
        cp16(dst0 + SW128(o), src + (size_t)row * ld + kofs + seg * 8);
    }
}

// ---------------------------------------------------------------------------
// GEMM1: y1[n,s,d] = relu( x[n,s,:] . wd[n,d,:] + bd[n,d] )
// grid: n(16) x mt(16) x nt(2)
// ---------------------------------------------------------------------------
__global__ __launch_bounds__(256) void gemm1_kernel(const float* __restrict__ X) {
    extern __shared__ __align__(1024) char sm[];
    uint32_t sbase = smem_u32(sm);
    int tid = threadIdx.x;
    WarpId w{tid & 31, (tid >> 5) & 3, tid >> 7};

    int n  = blockIdx.x >> 5;
    int mt = (blockIdx.x >> 1) & 15;
    int nt = blockIdx.x & 1;

    const float* Xa = X + (size_t)(n * SQ + mt * 128) * HH;
    const __nv_bfloat16* Bw = g_wd + (size_t)n * DB * HH + (size_t)(nt * 128) * HH;
    float* bias_s = reinterpret_cast<float*>(sm + OFF_BIAS);
    if (tid < 128) bias_s[tid] = g_bd[n * DB + nt * 128 + tid];

    float acc[2][8][4];
#pragma unroll
    for (int i = 0; i < 2; ++i)
#pragma unroll
        for (int j = 0; j < 8; ++j)
#pragma unroll
            for (int k = 0; k < 4; ++k) acc[i][j][k] = 0.f;

    float4 areg[8];
    auto ldgA = [&](int c) {
#pragma unroll
        for (int i = 0; i < 8; ++i) {
            int idx = tid + i * 256;
            int row = idx >> 4, c4 = idx & 15;
            areg[i] = *reinterpret_cast<const float4*>(Xa + (size_t)row * HH + c * 64 + c4 * 4);
        }
    };
    auto stsA = [&](int s) {
        uint32_t ab = sbase + (uint32_t)s * STG_SZ;
#pragma unroll
        for (int i = 0; i < 8; ++i) {
            int idx = tid + i * 256;
            int row = idx >> 4, c4 = idx & 15;
            uint2 v;
            v.x = packbf2(areg[i].x, areg[i].y);
            v.y = packbf2(areg[i].z, areg[i].w);
            uint32_t o = (uint32_t)(row * 128 + c4 * 8);
            *reinterpret_cast<uint2*>(sm + (ab - sbase) + SW128(o)) = v;
        }
    };

    // prologue: stage 0
    ldgA(0);
    cp_tile(sbase, OFF_B0, 0, Bw, HH, 0, tid);
    CP_COMMIT();
    stsA(0);
    cp_wait<0>();
    __syncthreads();

    constexpr int NC = HH / 64;   // 16
    for (int c = 0; c < NC; ++c) {
        int s = c & 1;
        if (c + 1 < NC) {
            ldgA(c + 1);
            cp_tile(sbase, OFF_B0, (c + 1) & 1, Bw, HH, (c + 1) * 64, tid);
            CP_COMMIT();
        }
        compute_stage(sbase, s, w, acc);
        if (c + 1 < NC) {
            stsA((c + 1) & 1);
            cp_wait<0>();
        }
        __syncthreads();
    }

    // epilogue: bias + relu -> bf16 smem (stride 136 halves = 272B), then coalesced copy
#pragma unroll
    for (int mi = 0; mi < 2; ++mi)
#pragma unroll
        for (int ni = 0; ni < 8; ++ni) {
            int r = w.wm * 32 + mi * 16 + (w.lane >> 2);
            int cpr = w.wn * 64 + ni * 8 + (w.lane & 3) * 2;
            float b0 = bias_s[cpr], b1 = bias_s[cpr + 1];
            float v0 = fmaxf(acc[mi][ni][0] + b0, 0.f);
            float v1 = fmaxf(acc[mi][ni][1] + b1, 0.f);
            float v2 = fmaxf(acc[mi][ni][2] + b0, 0.f);
            float v3 = fmaxf(acc[mi][ni][3] + b1, 0.f);
            *reinterpret_cast<uint32_t*>(sm + r * 272 + cpr * 2)       = packbf2(v0, v1);
            *reinterpret_cast<uint32_t*>(sm + (r + 8) * 272 + cpr * 2) = packbf2(v2, v3);
        }
    __syncthreads();
    __nv_bfloat16* y1b = g_y1 + (size_t)(n * SQ + mt * 128) * DB + nt * 128;
#pragma unroll
    for (int i = 0; i < 8; ++i) {
        int idx = tid + i * 256;
        int row = idx >> 4, seg = idx & 15;
        uint4 v = *reinterpret_cast<const uint4*>(sm + row * 272 + seg * 16);
        *reinterpret_cast<uint4*>(y1b + (size_t)row * DB + seg * 8) = v;
    }
}

// ---------------------------------------------------------------------------
// GEMM2: out[n,s,h] = x[n,s,h] + y1[n,s,:] . wu[n,h,:] + bu[n,h]
// grid: n(16) x mt(16) x nt(8)
// ---------------------------------------------------------------------------
__global__ __launch_bounds__(256, 2) void gemm2_kernel(const float* __restrict__ X,
                                                       float* __restrict__ Out) {
    extern __shared__ __align__(1024) char sm[];
    uint32_t sbase = smem_u32(sm);
    int tid = threadIdx.x;
    WarpId w{tid & 31, (tid >> 5) & 3, tid >> 7};

    int n  = blockIdx.x >> 7;
    int mt = (blockIdx.x >> 3) & 15;
    int nt = blockIdx.x & 7;

    const __nv_bfloat16* Aa = g_y1 + (size_t)(n * SQ + mt * 128) * DB;
    const __nv_bfloat16* Bw = g_wu + (size_t)(n * HH + nt * 128) * DB;
    float* bias_s = reinterpret_cast<float*>(sm + OFF_BIAS);
    if (tid < 128) bias_s[tid] = g_bu[n * HH + nt * 128 + tid];

    float acc[2][8][4];
#pragma unroll
    for (int i = 0; i < 2; ++i)
#pragma unroll
        for (int j = 0; j < 8; ++j)
#pragma unroll
            for (int k = 0; k < 4; ++k) acc[i][j][k] = 0.f;

    cp_tile(sbase, 0,      0, Aa, DB, 0, tid);
    cp_tile(sbase, OFF_B0, 0, Bw, DB, 0, tid);
    CP_COMMIT();

    constexpr int NC = DB / 64;   // 4
    for (int c = 0; c < NC; ++c) {
        if (c + 1 < NC) {
            cp_tile(sbase, 0,      (c + 1) & 1, Aa, DB, (c + 1) * 64, tid);
            cp_tile(sbase, OFF_B0, (c + 1) & 1, Bw, DB, (c + 1) * 64, tid);
            CP_COMMIT();
            cp_wait<1>();
        } else {
            cp_wait<0>();
        }
        __syncthreads();
        compute_stage(sbase, c & 1, w, acc);
        __syncthreads();
    }

    // epilogue: two 64-col halves through smem (fp32, stride 68 floats = 272B)
    size_t rowbase = (size_t)(n * SQ + mt * 128);
    for (int h = 0; h < 2; ++h) {
        if (w.wn == h) {
#pragma unroll
            for (int mi = 0; mi < 2; ++mi)
#pragma unroll
                for (int ni = 0; ni < 8; ++ni) {
                    int r = w.wm * 32 + mi * 16 + (w.lane >> 2);
                    int cc = ni * 8 + (w.lane & 3) * 2;
                    float b0 = bias_s[h * 64 + cc], b1 = bias_s[h * 64 + cc + 1];
                    float2 p0 = make_float2(acc[mi][ni][0] + b0, acc[mi][ni][1] + b1);
                    float2 p1 = make_float2(acc[mi][ni][2] + b0, acc[mi][ni][3] + b1);
                    *reinterpret_cast<float2*>(sm + r * 272 + cc * 4)       = p0;
                    *reinterpret_cast<float2*>(sm + (r + 8) * 272 + cc * 4) = p1;
                }
        }
        __syncthreads();
#pragma unroll
        for (int i = 0; i < 8; ++i) {
            int idx = tid + i * 256;
            int row = idx >> 4, seg = idx & 15;
            size_t g = (rowbase + row) * HH + nt * 128 + h * 64 + seg * 4;
            float4 xv = *reinterpret_cast<const float4*>(X + g);
            float4 rv = *reinterpret_cast<const float4*>(sm + row * 272 + seg * 16);
            float4 o;
            o.x = xv.x + rv.x; o.y = xv.y + rv.y;
            o.z = xv.z + rv.z; o.w = xv.w + rv.w;
            *reinterpret_cast<float4*>(Out + g) = o;
        }
        __syncthreads();
    }
}

// ---------------------------------------------------------------------------
// Launch
// ---------------------------------------------------------------------------
extern "C" void kernel_launch(void* const* d_in, const int* in_sizes, int n_in,
                              void* d_out, int out_size) {
    const float* X    = (const float*)d_in[0];
    const float* prob = (const float*)d_in[1];
    const float* wd   = (const float*)d_in[2];
    const float* bd   = (const float*)d_in[3];
    const float* wu   = (const float*)d_in[4];
    const float* bu   = (const float*)d_in[5];
    float* out = (float*)d_out;

    static bool attr_done = false;
    if (!attr_done) {
        cudaFuncSetAttribute(gemm1_kernel, cudaFuncAttributeMaxDynamicSharedMemorySize, SMEM_TOTAL);
        cudaFuncSetAttribute(gemm2_kernel, cudaFuncAttributeMaxDynamicSharedMemorySize, SMEM_TOTAL);
        attr_done = true;
    }

    merge_wd_kernel<<<E2 / 256, 256>>>(wd, prob);
    merge_wu_kernel<<<E2 / 256, 256>>>(wu, prob);
    merge_b_kernel<<<(NI * (DB + HH) + 255) / 256, 256>>>(bd, bu, prob);

    gemm1_kernel<<<NI * 16 * 2, 256, SMEM_TOTAL>>>(X);
    gemm2_kernel<<<NI * 16 * 8, 256, SMEM_TOTAL>>>(X, out);
}